// round 1
// baseline (speedup 1.0000x reference)
#include <cuda_runtime.h>
#include <math.h>

// Shapes
// B=2 T=8 H=128 W=192 C=96 NH=2 KD=8 HK=16 MH=MW=8 NWH=16 NWW=24
// token stride: w:96, h:18432, t:2359296, b:18874368; total 37748736 floats

__device__ float g_y1[37748736];  // scratch: post-spatial / post-temporal activations

#define SCALE 0.35355339059327373f
#define EPSLN 1e-3f

// ---------------------------------------------------------------------------
// Kernel 1: LN1 + shifted-window MHA.  grid = B*T*384 = 6144, block = 128
// dynamic smem layout (floats):
//  xs      0     64*100   LN'd tokens (padded stride 100)
//  wq   6400     16*96    transposed [hk][c]
//  wk   7936     16*96
//  wv   9472     16*96
//  wo  11008     16*96    (natural layout of Wo)
//  bq  12544 16 | bk 12560 16 | bv 12576 16 | bo 12592 96 | g1 12688 96 | b1 12784 96
//  qs  12880     64*20
//  ks  14160     64*20
//  vs  15440     64*20
//  os  16720     64*20
//  mu  18000 64 | rs 18064 64 | tof 18128 64 (int)
//  total 18192 floats = 72768 B
// ---------------------------------------------------------------------------
__global__ void __launch_bounds__(128, 1) k_win(
    const float* __restrict__ x,
    const float* __restrict__ g1, const float* __restrict__ b1,
    const float* __restrict__ Wq, const float* __restrict__ bq,
    const float* __restrict__ Wk, const float* __restrict__ bk,
    const float* __restrict__ Wv, const float* __restrict__ bv,
    const float* __restrict__ Wo, const float* __restrict__ bo)
{
    extern __shared__ float sm[];
    float* xs   = sm;
    float* wq   = sm + 6400;
    float* wk   = sm + 7936;
    float* wv   = sm + 9472;
    float* wo   = sm + 11008;
    float* bq_s = sm + 12544;
    float* bk_s = sm + 12560;
    float* bv_s = sm + 12576;
    float* bo_s = sm + 12592;
    float* g1_s = sm + 12688;
    float* b1_s = sm + 12784;
    float* qs   = sm + 12880;
    float* ks_  = sm + 14160;
    float* vs   = sm + 15440;
    float* os   = sm + 16720;
    float* mu_s = sm + 18000;
    float* rs_s = sm + 18064;
    int*   tof  = (int*)(sm + 18128);

    const int tid  = threadIdx.x;
    const int blk  = blockIdx.x;
    const int bt   = blk / 384;
    const int wrem = blk - bt * 384;
    const int wh   = wrem / 24, ww = wrem - (wrem / 24) * 24;

    // stage weights; transpose Wq/Wk/Wv to [hk][c]
    for (int i = tid; i < 1536; i += 128) {
        int c = i >> 4, hk = i & 15;
        int tpos = hk * 96 + c;
        wq[tpos] = Wq[i];
        wk[tpos] = Wk[i];
        wv[tpos] = Wv[i];
        wo[i]    = Wo[i];
    }
    if (tid < 16) { bq_s[tid] = bq[tid]; bk_s[tid] = bk[tid]; bv_s[tid] = bv[tid]; }
    if (tid < 96) { bo_s[tid] = bo[tid]; g1_s[tid] = g1[tid]; b1_s[tid] = b1[tid]; }
    if (tid < 64) {
        int i = tid >> 3, j = tid & 7;
        int h = (wh * 8 + i + 4) & 127;
        int w = ww * 8 + j + 4; if (w >= 192) w -= 192;
        tof[tid] = bt * 2359296 + h * 18432 + w * 96;
    }
    __syncthreads();

    // load 64 token rows (96 floats each) as float4
    for (int idx = tid; idx < 64 * 24; idx += 128) {
        int tok = idx / 24, v = idx - (idx / 24) * 24;
        *(float4*)(xs + tok * 100 + v * 4) = *(const float4*)(x + tof[tok] + v * 4);
    }
    __syncthreads();

    // LN stats per token
    if (tid < 64) {
        const float* xr = xs + tid * 100;
        float s = 0.f, ss = 0.f;
        #pragma unroll
        for (int c = 0; c < 96; c++) { float v = xr[c]; s += v; ss += v * v; }
        float mu  = s * (1.f / 96.f);
        float var = ss * (1.f / 96.f) - mu * mu;
        mu_s[tid] = mu;
        rs_s[tid] = rsqrtf(var + EPSLN);
    }
    __syncthreads();
    {
        int tok = tid >> 1, c0 = (tid & 1) * 48;
        float mu = mu_s[tok], rs = rs_s[tok];
        float* xr = xs + tok * 100;
        #pragma unroll 8
        for (int c2 = 0; c2 < 48; c2++) {
            int c = c0 + c2;
            xr[c] = (xr[c] - mu) * rs * g1_s[c] + b1_s[c];
        }
    }
    __syncthreads();

    // QKV: each thread -> (token, 8 hk dims of q,k,v)
    {
        int tok = tid & 63, hk0 = (tid >> 6) * 8;
        float acc[24];
        #pragma unroll
        for (int u = 0; u < 8; u++) {
            acc[u]      = bq_s[hk0 + u];
            acc[8 + u]  = bk_s[hk0 + u];
            acc[16 + u] = bv_s[hk0 + u];
        }
        const float* xr = xs + tok * 100;
        #pragma unroll 4
        for (int c4 = 0; c4 < 24; c4++) {
            float4 xv = *(const float4*)(xr + c4 * 4);
            #pragma unroll
            for (int u = 0; u < 8; u++) {
                float4 a = *(const float4*)(wq + (hk0 + u) * 96 + c4 * 4);
                acc[u]      += xv.x * a.x + xv.y * a.y + xv.z * a.z + xv.w * a.w;
                float4 b2_ = *(const float4*)(wk + (hk0 + u) * 96 + c4 * 4);
                acc[8 + u]  += xv.x * b2_.x + xv.y * b2_.y + xv.z * b2_.z + xv.w * b2_.w;
                float4 cc = *(const float4*)(wv + (hk0 + u) * 96 + c4 * 4);
                acc[16 + u] += xv.x * cc.x + xv.y * cc.y + xv.z * cc.z + xv.w * cc.w;
            }
        }
        #pragma unroll
        for (int u = 0; u < 8; u++) {
            qs[tok * 20 + hk0 + u]  = acc[u];
            ks_[tok * 20 + hk0 + u] = acc[8 + u];
            vs[tok * 20 + hk0 + u]  = acc[16 + u];
        }
    }
    __syncthreads();

    // attention: thread -> (head, row); scores in registers
    {
        int n = tid & 63, hoff = (tid >> 6) * 8;
        float4 qa = *(const float4*)(qs + n * 20 + hoff);
        float4 qb = *(const float4*)(qs + n * 20 + hoff + 4);
        float sc[64];
        float mx = -1e30f;
        #pragma unroll
        for (int m = 0; m < 64; m++) {
            float4 ka = *(const float4*)(ks_ + m * 20 + hoff);
            float4 kb = *(const float4*)(ks_ + m * 20 + hoff + 4);
            float d = qa.x * ka.x + qa.y * ka.y + qa.z * ka.z + qa.w * ka.w
                    + qb.x * kb.x + qb.y * kb.y + qb.z * kb.z + qb.w * kb.w;
            d *= SCALE;
            sc[m] = d;
            mx = fmaxf(mx, d);
        }
        float o8[8];
        #pragma unroll
        for (int u = 0; u < 8; u++) o8[u] = 0.f;
        float sum = 0.f;
        #pragma unroll
        for (int m = 0; m < 64; m++) {
            float e = __expf(sc[m] - mx);
            sum += e;
            float4 va = *(const float4*)(vs + m * 20 + hoff);
            float4 vb = *(const float4*)(vs + m * 20 + hoff + 4);
            o8[0] += e * va.x; o8[1] += e * va.y; o8[2] += e * va.z; o8[3] += e * va.w;
            o8[4] += e * vb.x; o8[5] += e * vb.y; o8[6] += e * vb.z; o8[7] += e * vb.w;
        }
        float inv = 1.f / sum;
        #pragma unroll
        for (int u = 0; u < 8; u++) os[n * 20 + hoff + u] = o8[u] * inv;
    }
    __syncthreads();

    // output projection + scatter (shift-inverse == same index map)
    {
        int n = tid >> 1, c0 = (tid & 1) * 48;
        float o[16];
        #pragma unroll
        for (int u = 0; u < 4; u++) {
            float4 t = *(const float4*)(os + n * 20 + u * 4);
            o[u * 4] = t.x; o[u * 4 + 1] = t.y; o[u * 4 + 2] = t.z; o[u * 4 + 3] = t.w;
        }
        float* yp = g_y1 + tof[n] + c0;
        #pragma unroll 4
        for (int cc = 0; cc < 48; cc += 4) {
            float4 r = make_float4(bo_s[c0 + cc], bo_s[c0 + cc + 1],
                                   bo_s[c0 + cc + 2], bo_s[c0 + cc + 3]);
            #pragma unroll
            for (int hk = 0; hk < 16; hk++) {
                float4 w4 = *(const float4*)(wo + hk * 96 + c0 + cc);
                r.x += o[hk] * w4.x; r.y += o[hk] * w4.y;
                r.z += o[hk] * w4.z; r.w += o[hk] * w4.w;
            }
            *(float4*)(yp + cc) = r;
        }
    }
}

// ---------------------------------------------------------------------------
// Kernel 2: temporal MHA, in-place on g_y1.  grid = 6144, block = 256 (8 warps,
// one (b,h,w) location per warp, T=8 tokens).
// smem (floats): wq 0, wk 1536, wv 3072, wo 4608, bq 6144, bk 6160, bv 6176,
//   bo 6192(96), xw 6288 (8 warps * 8*100), qkv 12688 (8 * 480), ow 16528 (8*160)
//   total 17808 floats = 71232 B
// ---------------------------------------------------------------------------
__global__ void __launch_bounds__(256, 1) k_time(
    const float* __restrict__ Wq, const float* __restrict__ bq,
    const float* __restrict__ Wk, const float* __restrict__ bk,
    const float* __restrict__ Wv, const float* __restrict__ bv,
    const float* __restrict__ Wo, const float* __restrict__ bo)
{
    extern __shared__ float sm[];
    float* wq   = sm;
    float* wk   = sm + 1536;
    float* wv   = sm + 3072;
    float* wo   = sm + 4608;
    float* bq_s = sm + 6144;
    float* bk_s = sm + 6160;
    float* bv_s = sm + 6176;
    float* bo_s = sm + 6192;

    const int tid = threadIdx.x, warp = tid >> 5, lane = tid & 31;

    for (int i = tid; i < 1536; i += 256) {
        int c = i >> 4, hk = i & 15;
        int tpos = hk * 96 + c;
        wq[tpos] = Wq[i]; wk[tpos] = Wk[i]; wv[tpos] = Wv[i];
        wo[i] = Wo[i];
    }
    if (tid < 16) { bq_s[tid] = bq[tid]; bk_s[tid] = bk[tid]; bv_s[tid] = bv[tid]; }
    if (tid < 96) { bo_s[tid] = bo[tid]; }
    __syncthreads();

    float* xw = sm + 6288 + warp * 800;    // [8][100]
    float* qw = sm + 12688 + warp * 480;   // [8][20]
    float* kw = qw + 160;
    float* vw = qw + 320;
    float* ow = sm + 16528 + warp * 160;   // [8][20]

    const int loc = blockIdx.x * 8 + warp;          // < 49152
    const int bb  = loc / 24576;
    const int rem = loc - bb * 24576;
    const int h   = rem / 192, w = rem - (rem / 192) * 192;
    const int base = bb * 18874368 + h * 18432 + w * 96;

    // load 8 temporal rows
    for (int idx = lane; idx < 192; idx += 32) {
        int t = idx / 24, v = idx - (idx / 24) * 24;
        *(float4*)(xw + t * 100 + v * 4) =
            *(const float4*)(g_y1 + base + t * 2359296 + v * 4);
    }
    __syncwarp();

    // QKV: 24 lanes, (token, matrix)
    if (lane < 24) {
        int t = lane & 7, mat = lane >> 3;
        const float* wp = (mat == 0) ? wq : (mat == 1) ? wk : wv;
        const float* bp = (mat == 0) ? bq_s : (mat == 1) ? bk_s : bv_s;
        float* outp = ((mat == 0) ? qw : (mat == 1) ? kw : vw) + t * 20;
        float acc[16];
        #pragma unroll
        for (int u = 0; u < 16; u++) acc[u] = bp[u];
        const float* xr = xw + t * 100;
        #pragma unroll 4
        for (int c4 = 0; c4 < 24; c4++) {
            float4 xv = *(const float4*)(xr + c4 * 4);
            #pragma unroll
            for (int u = 0; u < 16; u++) {
                float4 w4 = *(const float4*)(wp + u * 96 + c4 * 4);
                acc[u] += xv.x * w4.x + xv.y * w4.y + xv.z * w4.z + xv.w * w4.w;
            }
        }
        #pragma unroll
        for (int u = 0; u < 16; u++) outp[u] = acc[u];
    }
    __syncwarp();

    // attention: 16 lanes, (head, row)
    if (lane < 16) {
        int n = lane & 7, hoff = (lane >> 3) * 8;
        float4 qa = *(const float4*)(qw + n * 20 + hoff);
        float4 qb = *(const float4*)(qw + n * 20 + hoff + 4);
        float sc[8];
        float mx = -1e30f;
        #pragma unroll
        for (int m = 0; m < 8; m++) {
            float4 ka = *(const float4*)(kw + m * 20 + hoff);
            float4 kb = *(const float4*)(kw + m * 20 + hoff + 4);
            float d = qa.x * ka.x + qa.y * ka.y + qa.z * ka.z + qa.w * ka.w
                    + qb.x * kb.x + qb.y * kb.y + qb.z * kb.z + qb.w * kb.w;
            d *= SCALE;
            sc[m] = d;
            mx = fmaxf(mx, d);
        }
        float o8[8];
        #pragma unroll
        for (int u = 0; u < 8; u++) o8[u] = 0.f;
        float sum = 0.f;
        #pragma unroll
        for (int m = 0; m < 8; m++) {
            float e = __expf(sc[m] - mx);
            sum += e;
            float4 va = *(const float4*)(vw + m * 20 + hoff);
            float4 vb = *(const float4*)(vw + m * 20 + hoff + 4);
            o8[0] += e * va.x; o8[1] += e * va.y; o8[2] += e * va.z; o8[3] += e * va.w;
            o8[4] += e * vb.x; o8[5] += e * vb.y; o8[6] += e * vb.z; o8[7] += e * vb.w;
        }
        float inv = 1.f / sum;
        #pragma unroll
        for (int u = 0; u < 8; u++) ow[n * 20 + hoff + u] = o8[u] * inv;
    }
    __syncwarp();

    // projection, write back in place
    {
        int t = lane >> 2, c0 = (lane & 3) * 24;
        float o[16];
        #pragma unroll
        for (int u = 0; u < 4; u++) {
            float4 tt = *(const float4*)(ow + t * 20 + u * 4);
            o[u * 4] = tt.x; o[u * 4 + 1] = tt.y; o[u * 4 + 2] = tt.z; o[u * 4 + 3] = tt.w;
        }
        float* yp = g_y1 + base + t * 2359296 + c0;
        #pragma unroll
        for (int cc = 0; cc < 24; cc += 4) {
            float4 r = make_float4(bo_s[c0 + cc], bo_s[c0 + cc + 1],
                                   bo_s[c0 + cc + 2], bo_s[c0 + cc + 3]);
            #pragma unroll
            for (int hk = 0; hk < 16; hk++) {
                float4 w4 = *(const float4*)(wo + hk * 96 + c0 + cc);
                r.x += o[hk] * w4.x; r.y += o[hk] * w4.y;
                r.z += o[hk] * w4.z; r.w += o[hk] * w4.w;
            }
            *(float4*)(yp + cc) = r;
        }
    }
}

// ---------------------------------------------------------------------------
// Kernel 3: LN2 + MLP (relu(xW1+b) -> relu(hW2+b)).  grid = 1536, block = 256.
// smem (floats): w1 0 (9216), w2 9216 (9216), b1m 18432, b2m 18528, g2 18624,
//   b2 18720, xw 18816 (8 warps * 800). total 25216 floats = 100864 B
// warp handles 8 tokens per iteration; lane owns tokens {tp, tp+4}, dims dg*12..+12
// ---------------------------------------------------------------------------
__global__ void __launch_bounds__(256, 1) k_mlp(
    const float* __restrict__ g2, const float* __restrict__ b2,
    const float* __restrict__ W1, const float* __restrict__ b1m,
    const float* __restrict__ W2, const float* __restrict__ b2m,
    float* __restrict__ out)
{
    extern __shared__ float sm[];
    float* w1s  = sm;
    float* w2s  = sm + 9216;
    float* b1ms = sm + 18432;
    float* b2ms = sm + 18528;
    float* g2s  = sm + 18624;
    float* b2s  = sm + 18720;

    const int tid = threadIdx.x, warp = tid >> 5, lane = tid & 31;

    for (int i = tid; i < 9216; i += 256) { w1s[i] = W1[i]; w2s[i] = W2[i]; }
    if (tid < 96) {
        b1ms[tid] = b1m[tid]; b2ms[tid] = b2m[tid];
        g2s[tid]  = g2[tid];  b2s[tid]  = b2[tid];
    }
    __syncthreads();

    float* xw = sm + 18816 + warp * 800;   // [8][100]

    const int tt = lane >> 2, cq = (lane & 3) * 24;   // LN mapping
    const int tp = lane >> 3, dg = lane & 7;          // GEMM mapping

    for (int g = blockIdx.x * 8 + warp; g < 49152; g += gridDim.x * 8) {
        const int base = g * 768;

        // load + LN2
        float s = 0.f, ss = 0.f;
        float4 buf[6];
        #pragma unroll
        for (int v = 0; v < 6; v++) {
            float4 d = *(const float4*)(g_y1 + base + tt * 96 + cq + v * 4);
            buf[v] = d;
            s  += d.x + d.y + d.z + d.w;
            ss += d.x * d.x + d.y * d.y + d.z * d.z + d.w * d.w;
        }
        s  += __shfl_xor_sync(0xffffffffu, s, 1);
        ss += __shfl_xor_sync(0xffffffffu, ss, 1);
        s  += __shfl_xor_sync(0xffffffffu, s, 2);
        ss += __shfl_xor_sync(0xffffffffu, ss, 2);
        float mu = s * (1.f / 96.f);
        float rs = rsqrtf(ss * (1.f / 96.f) - mu * mu + EPSLN);
        #pragma unroll
        for (int v = 0; v < 6; v++) {
            int c = cq + v * 4;
            float4 d = buf[v];
            d.x = (d.x - mu) * rs * g2s[c]     + b2s[c];
            d.y = (d.y - mu) * rs * g2s[c + 1] + b2s[c + 1];
            d.z = (d.z - mu) * rs * g2s[c + 2] + b2s[c + 2];
            d.w = (d.w - mu) * rs * g2s[c + 3] + b2s[c + 3];
            *(float4*)(xw + tt * 100 + c) = d;
        }
        __syncwarp();

        // layer 1
        float a0[12], a1[12];
        #pragma unroll
        for (int j = 0; j < 12; j++) { a0[j] = b1ms[dg * 12 + j]; a1[j] = a0[j]; }
        #pragma unroll 8
        for (int k = 0; k < 96; k++) {
            float x0 = xw[tp * 100 + k];
            float x1 = xw[(tp + 4) * 100 + k];
            #pragma unroll
            for (int j4 = 0; j4 < 3; j4++) {
                float4 w4 = *(const float4*)(w1s + k * 96 + dg * 12 + j4 * 4);
                a0[j4 * 4 + 0] += x0 * w4.x; a0[j4 * 4 + 1] += x0 * w4.y;
                a0[j4 * 4 + 2] += x0 * w4.z; a0[j4 * 4 + 3] += x0 * w4.w;
                a1[j4 * 4 + 0] += x1 * w4.x; a1[j4 * 4 + 1] += x1 * w4.y;
                a1[j4 * 4 + 2] += x1 * w4.z; a1[j4 * 4 + 3] += x1 * w4.w;
            }
        }
        __syncwarp();
        #pragma unroll
        for (int j = 0; j < 12; j++) {
            xw[tp * 100 + dg * 12 + j]       = fmaxf(a0[j], 0.f);
            xw[(tp + 4) * 100 + dg * 12 + j] = fmaxf(a1[j], 0.f);
        }
        __syncwarp();

        // layer 2 -> global
        #pragma unroll
        for (int j = 0; j < 12; j++) { a0[j] = b2ms[dg * 12 + j]; a1[j] = a0[j]; }
        #pragma unroll 8
        for (int k = 0; k < 96; k++) {
            float x0 = xw[tp * 100 + k];
            float x1 = xw[(tp + 4) * 100 + k];
            #pragma unroll
            for (int j4 = 0; j4 < 3; j4++) {
                float4 w4 = *(const float4*)(w2s + k * 96 + dg * 12 + j4 * 4);
                a0[j4 * 4 + 0] += x0 * w4.x; a0[j4 * 4 + 1] += x0 * w4.y;
                a0[j4 * 4 + 2] += x0 * w4.z; a0[j4 * 4 + 3] += x0 * w4.w;
                a1[j4 * 4 + 0] += x1 * w4.x; a1[j4 * 4 + 1] += x1 * w4.y;
                a1[j4 * 4 + 2] += x1 * w4.z; a1[j4 * 4 + 3] += x1 * w4.w;
            }
        }
        #pragma unroll
        for (int j4 = 0; j4 < 3; j4++) {
            float4 r0 = make_float4(fmaxf(a0[j4 * 4 + 0], 0.f), fmaxf(a0[j4 * 4 + 1], 0.f),
                                    fmaxf(a0[j4 * 4 + 2], 0.f), fmaxf(a0[j4 * 4 + 3], 0.f));
            float4 r1 = make_float4(fmaxf(a1[j4 * 4 + 0], 0.f), fmaxf(a1[j4 * 4 + 1], 0.f),
                                    fmaxf(a1[j4 * 4 + 2], 0.f), fmaxf(a1[j4 * 4 + 3], 0.f));
            *(float4*)(out + base + tp * 96 + dg * 12 + j4 * 4)       = r0;
            *(float4*)(out + base + (tp + 4) * 96 + dg * 12 + j4 * 4) = r1;
        }
        __syncwarp();
    }
}

// ---------------------------------------------------------------------------
extern "C" void kernel_launch(void* const* d_in, const int* in_sizes, int n_in,
                              void* d_out, int out_size)
{
    const float* x   = (const float*)d_in[0];
    const float* g1  = (const float*)d_in[1];
    const float* b1  = (const float*)d_in[2];
    const float* g2  = (const float*)d_in[3];
    const float* b2  = (const float*)d_in[4];
    const float* Wq  = (const float*)d_in[5];
    const float* bq  = (const float*)d_in[6];
    const float* Wk  = (const float*)d_in[7];
    const float* bk  = (const float*)d_in[8];
    const float* Wv  = (const float*)d_in[9];
    const float* bv  = (const float*)d_in[10];
    const float* Wo  = (const float*)d_in[11];
    const float* bo  = (const float*)d_in[12];
    const float* W1  = (const float*)d_in[13];
    const float* b1m = (const float*)d_in[14];
    const float* W2  = (const float*)d_in[15];
    const float* b2m = (const float*)d_in[16];
    float* out = (float*)d_out;

    cudaFuncSetAttribute(k_win,  cudaFuncAttributeMaxDynamicSharedMemorySize, 72768);
    cudaFuncSetAttribute(k_time, cudaFuncAttributeMaxDynamicSharedMemorySize, 71232);
    cudaFuncSetAttribute(k_mlp,  cudaFuncAttributeMaxDynamicSharedMemorySize, 100864);

    k_win <<<6144, 128, 72768>>>(x, g1, b1, Wq, bq, Wk, bk, Wv, bv, Wo, bo);
    k_time<<<6144, 256, 71232>>>(Wq, bq, Wk, bk, Wv, bv, Wo, bo);
    k_mlp <<<1536, 256, 100864>>>(g2, b2, W1, b1m, W2, b2m, out);
}